// round 5
// baseline (speedup 1.0000x reference)
#include <cuda_runtime.h>
#include <math.h>

#define M_ROWS 512
#define K_COMP 8
#define B_PTS  4096
#define B_QTR  1024
#define PHI_DIM 120
#define Z_COLS 80
#define LOG2PI_F 1.8378770664093453f
#define LOG2E_F  1.4426950408889634f

#define NBLK    444      // 148 SMs x 3 CTAs (guaranteed resident via launch_bounds)
#define N_ITEMS 2048     // 512 m x 4 quarters

// Scratch (device globals — no allocation allowed)
__device__ float g_zT[72][M_ROWS];            // columns 0..71, column-major
__device__ float g_respT[4][K_COMP][M_ROWS];  // partial resp sums per quarter
__device__ unsigned g_ticket;                 // work tickets (reset to 0 each run)
__device__ unsigned g_arrive;                 // barrier arrivals
__device__ unsigned g_done;                   // completion counter

__device__ __forceinline__ float ex2f(float x) {
    float r; asm("ex2.approx.f32 %0, %1;" : "=f"(r) : "f"(x)); return r;
}
__device__ __forceinline__ float rcpf(float x) {
    float r; asm("rcp.approx.f32 %0, %1;" : "=f"(r) : "f"(x)); return r;
}

// ---------------------------------------------------------------------------
// One persistent kernel: ticketed (m,quarter) items -> grid barrier -> norm.
// ---------------------------------------------------------------------------
__global__ void __launch_bounds__(128, 3) gmm_all(const float* __restrict__ phi,
                                                  const float4* __restrict__ X,
                                                  float* __restrict__ out) {
    const int tid = threadIdx.x;
    const unsigned lane = tid & 31;
    const unsigned wid = tid >> 5;
    const int par = tid & 1;          // parity: 0 -> k0..3, 1 -> k4..7
    const int kbase = par * 4;

    __shared__ float sp[K_COMP][15];
    __shared__ float sred[4][2][4];
    __shared__ unsigned s_item;

    // =====================  PHASE 1: (m, quarter) items  =====================
    for (;;) {
        if (tid == 0) s_item = atomicAdd(&g_ticket, 1u);
        __syncthreads();
        unsigned item = s_item;
        if (item >= N_ITEMS) break;
        const int m = item >> 2;
        const int q = item & 3;

        // ---- prep: threads 0..7, one k each ----
        if (tid < K_COMP) {
            const int k = tid;
            const float* pm = phi + m * PHI_DIM;

            float mx = -INFINITY;
            #pragma unroll
            for (int j = 0; j < K_COMP; j++) mx = fmaxf(mx, pm[j]);
            float s = 0.f;
            #pragma unroll
            for (int j = 0; j < K_COMP; j++) s += __expf(pm[j] - mx);
            float pik = __expf(pm[k] - mx) / s;

            float mu0 = pm[8 + k * 4 + 0];
            float mu1 = pm[8 + k * 4 + 1];
            float mu2 = pm[8 + k * 4 + 2];
            float mu3 = pm[8 + k * 4 + 3];

            const float* lv = pm + 40 + k * 10;
            float L00 = lv[0], L10 = lv[1], L11 = lv[2], L20 = lv[3], L21 = lv[4];
            float L22 = lv[5], L30 = lv[6], L31 = lv[7], L32 = lv[8], L33 = lv[9];

            float G00 = 1.0f / L00, G11 = 1.0f / L11, G22 = 1.0f / L22, G33 = 1.0f / L33;
            float G10 = -L10 * G00 * G11;
            float G21 = -L21 * G11 * G22;
            float G20 = -(L20 * G00 + L21 * G10) * G22;
            float G32 = -L32 * G22 * G33;
            float G31 = -(L31 * G11 + L32 * G21) * G33;
            float G30 = -(L30 * G00 + L31 * G10 + L32 * G20) * G33;

            const float sc = sqrtf(0.5f * LOG2E_F);
            float A00 = sc * G00, A10 = sc * G10, A11 = sc * G11;
            float A20 = sc * G20, A21 = sc * G21, A22 = sc * G22;
            float A30 = sc * G30, A31 = sc * G31, A32 = sc * G32, A33 = sc * G33;

            sp[k][0] = A00; sp[k][1] = A10; sp[k][2] = A11; sp[k][3] = A20;
            sp[k][4] = A21; sp[k][5] = A22; sp[k][6] = A30; sp[k][7] = A31;
            sp[k][8] = A32; sp[k][9] = A33;
            sp[k][10] = -(A00 * mu0);
            sp[k][11] = -(A10 * mu0 + A11 * mu1);
            sp[k][12] = -(A20 * mu0 + A21 * mu1 + A22 * mu2);
            sp[k][13] = -(A30 * mu0 + A31 * mu1 + A32 * mu2 + A33 * mu3);

            float log_det = 2.0f * (__logf(fmaxf(fabsf(L00), 1e-8f)) +
                                    __logf(fmaxf(fabsf(L11), 1e-8f)) +
                                    __logf(fmaxf(fabsf(L22), 1e-8f)) +
                                    __logf(fmaxf(fabsf(L33), 1e-8f)));
            float ckv = __logf(fmaxf(pik, 1e-8f)) - 0.5f * (4.0f * LOG2PI_F + log_det);
            sp[k][14] = ckv * LOG2E_F;

            if (q == 0) {
                g_zT[k * 4 + 0][m] = mu0;
                g_zT[k * 4 + 1][m] = mu1;
                g_zT[k * 4 + 2][m] = mu2;
                g_zT[k * 4 + 3][m] = mu3;
                g_zT[32 + k * 4 + 0][m] = __logf(fmaxf(fabsf(L00), 1e-6f));
                g_zT[32 + k * 4 + 1][m] = __logf(fmaxf(fabsf(L11), 1e-6f));
                g_zT[32 + k * 4 + 2][m] = __logf(fmaxf(fabsf(L22), 1e-6f));
                g_zT[32 + k * 4 + 3][m] = __logf(fmaxf(fabsf(L33), 1e-6f));
                g_zT[64 + k][m] = pik;
            }
        }
        __syncthreads();

        // ---- load my 4 k's params into registers ----
        float A00[4], A10[4], A11[4], A20[4], A21[4];
        float A22[4], A30[4], A31[4], A32[4], A33[4];
        float b0[4], b1[4], b2[4], b3[4], ck[4];
        #pragma unroll
        for (int kk = 0; kk < 4; kk++) {
            const float* s = sp[kbase + kk];
            A00[kk] = s[0]; A10[kk] = s[1]; A11[kk] = s[2];
            A20[kk] = s[3]; A21[kk] = s[4]; A22[kk] = s[5];
            A30[kk] = s[6]; A31[kk] = s[7]; A32[kk] = s[8]; A33[kk] = s[9];
            b0[kk] = s[10]; b1[kk] = s[11]; b2[kk] = s[12]; b3[kk] = s[13];
            ck[kk] = s[14];
        }

        float acc[4] = {0.f, 0.f, 0.f, 0.f};

        // lanes (2j,2j+1) form a pair handling the same point; 64 pairs/block.
        // 2 points per iteration for ILP -> 8 iterations over 1024 points.
        const int pair = tid >> 1;
        const int i0 = q * B_QTR + pair;
        #pragma unroll 2
        for (int it = 0; it < 8; it++) {
            #pragma unroll
            for (int u = 0; u < 2; u++) {
                float4 x = X[i0 + (it * 2 + u) * 64];
                float lj[4];
                #pragma unroll
                for (int kk = 0; kk < 4; kk++) {
                    float a0 = __fmaf_rn(x.x, A00[kk], b0[kk]);
                    float a1 = __fmaf_rn(x.x, A10[kk], __fmaf_rn(x.y, A11[kk], b1[kk]));
                    float a2 = __fmaf_rn(x.x, A20[kk],
                               __fmaf_rn(x.y, A21[kk], __fmaf_rn(x.z, A22[kk], b2[kk])));
                    float a3 = __fmaf_rn(x.x, A30[kk],
                               __fmaf_rn(x.y, A31[kk],
                               __fmaf_rn(x.z, A32[kk], __fmaf_rn(x.w, A33[kk], b3[kk]))));
                    float qq = __fmaf_rn(a0, a0,
                               __fmaf_rn(a1, a1, __fmaf_rn(a2, a2, a3 * a3)));
                    lj[kk] = ck[kk] - qq;
                }
                float mxh = fmaxf(fmaxf(lj[0], lj[1]), fmaxf(lj[2], lj[3]));
                float mx = fmaxf(mxh, __shfl_xor_sync(0xffffffffu, mxh, 1));
                float e0 = ex2f(lj[0] - mx), e1 = ex2f(lj[1] - mx);
                float e2 = ex2f(lj[2] - mx), e3 = ex2f(lj[3] - mx);
                float sh = (e0 + e1) + (e2 + e3);
                float stot = sh + __shfl_xor_sync(0xffffffffu, sh, 1);
                float inv = rcpf(stot);
                acc[0] = __fmaf_rn(e0, inv, acc[0]);
                acc[1] = __fmaf_rn(e1, inv, acc[1]);
                acc[2] = __fmaf_rn(e2, inv, acc[2]);
                acc[3] = __fmaf_rn(e3, inv, acc[3]);
            }
        }

        // ---- reduce: parity-preserving shuffles (strides 16,8,4,2) ----
        #pragma unroll
        for (int kk = 0; kk < 4; kk++) {
            float v = acc[kk];
            v += __shfl_down_sync(0xffffffffu, v, 16);
            v += __shfl_down_sync(0xffffffffu, v, 8);
            v += __shfl_down_sync(0xffffffffu, v, 4);
            v += __shfl_down_sync(0xffffffffu, v, 2);
            if (lane < 2) sred[wid][lane][kk] = v;
        }
        __syncthreads();
        if (tid < K_COMP) {
            int p = tid >> 2, idx = tid & 3;   // k = p*4 + idx = tid
            g_respT[q][tid][m] = sred[0][p][idx] + sred[1][p][idx] +
                                 sred[2][p][idx] + sred[3][p][idx];
        }
        __syncthreads();   // protect sp/sred/s_item reuse
    }

    // =====================  grid barrier  =====================
    __syncthreads();
    if (tid == 0) {
        __threadfence();
        atomicAdd(&g_arrive, 1u);
        volatile unsigned* p = &g_arrive;
        while (*p < NBLK) __nanosleep(128);
    }
    __syncthreads();
    __threadfence();

    // =====================  PHASE 2: standardization  =====================
    if (blockIdx.x < Z_COLS) {
        const int c = blockIdx.x;
        float v[4];
        if (c < 72) {
            const float* col = g_zT[c];
            #pragma unroll
            for (int j = 0; j < 4; j++) v[j] = col[tid + 128 * j];
        } else {
            const int k = c - 72;
            #pragma unroll
            for (int j = 0; j < 4; j++) {
                int r = tid + 128 * j;
                v[j] = (g_respT[0][k][r] + g_respT[1][k][r] +
                        g_respT[2][k][r] + g_respT[3][k][r]) * (1.0f / (float)B_PTS);
            }
        }

        __shared__ float nsh[4];
        __shared__ float n_mean, n_rstd;

        float s = (v[0] + v[1]) + (v[2] + v[3]);
        s += __shfl_down_sync(0xffffffffu, s, 16);
        s += __shfl_down_sync(0xffffffffu, s, 8);
        s += __shfl_down_sync(0xffffffffu, s, 4);
        s += __shfl_down_sync(0xffffffffu, s, 2);
        s += __shfl_down_sync(0xffffffffu, s, 1);
        if (lane == 0) nsh[wid] = s;
        __syncthreads();
        if (tid == 0) n_mean = (nsh[0] + nsh[1] + nsh[2] + nsh[3]) * (1.0f / (float)M_ROWS);
        __syncthreads();
        float mean = n_mean;

        float qsum = 0.f;
        #pragma unroll
        for (int j = 0; j < 4; j++) {
            v[j] -= mean;
            qsum = __fmaf_rn(v[j], v[j], qsum);
        }
        qsum += __shfl_down_sync(0xffffffffu, qsum, 16);
        qsum += __shfl_down_sync(0xffffffffu, qsum, 8);
        qsum += __shfl_down_sync(0xffffffffu, qsum, 4);
        qsum += __shfl_down_sync(0xffffffffu, qsum, 2);
        qsum += __shfl_down_sync(0xffffffffu, qsum, 1);
        __syncthreads();
        if (lane == 0) nsh[wid] = qsum;
        __syncthreads();
        if (tid == 0) {
            float var = (nsh[0] + nsh[1] + nsh[2] + nsh[3]) * (1.0f / (float)(M_ROWS - 1));
            n_rstd = 1.0f / fmaxf(sqrtf(var), 1e-6f);
        }
        __syncthreads();
        float rstd = n_rstd;
        #pragma unroll
        for (int j = 0; j < 4; j++) {
            int r = tid + 128 * j;
            out[r * Z_COLS + c] = v[j] * rstd;
        }
    }

    // =====================  counter reset (state -> 0 for graph replay) =====
    __syncthreads();
    if (tid == 0) {
        __threadfence();
        unsigned d = atomicAdd(&g_done, 1u);
        if (d == NBLK - 1) {
            g_ticket = 0u;
            g_arrive = 0u;
            g_done = 0u;
            __threadfence();
        }
    }
}

// ---------------------------------------------------------------------------
extern "C" void kernel_launch(void* const* d_in, const int* in_sizes, int n_in,
                              void* d_out, int out_size) {
    const float* phi = (const float*)d_in[0];
    const float4* X = (const float4*)d_in[1];
    float* out = (float*)d_out;

    gmm_all<<<NBLK, 128>>>(phi, X, out);
}